// round 10
// baseline (speedup 1.0000x reference)
#include <cuda_runtime.h>
#include <math.h>

#define N_NODES 100000
#define N_EDGES 6400000
#define F_IN    128
#define F_OUT   16

// ------------- device scratch (zero-init; invariants restored per call) ---
__device__ int   g_deg [N_NODES];            // in-deg from 0; k_dinv resets
__device__ float g_dinv[N_NODES];            // rsqrt(deg+1)
__device__ float g_g   [N_NODES * F_OUT];    // h=x@W (unscaled), then *dinv
__device__ float g_acc [N_NODES * F_OUT];    // scatter acc; zeroed in fused

// ---------------- K1: fused  gemm(h) || degree || zero  (R9-proven WIN) ----
#define GEMM_IDS 782
#define DEG_IDS  782
#define ZERO_IDS 391
#define FUSED_BLOCKS (GEMM_IDS + DEG_IDS + ZERO_IDS)   // 1955
#define DEG_STRIDE (DEG_IDS * 128)                      // 100096 threads

__global__ void __launch_bounds__(128) k_fused(const float* __restrict__ x,
                                               const float* __restrict__ W,
                                               const int* __restrict__ dst,
                                               float* __restrict__ out) {
    __shared__ float Ws[F_IN * F_OUT];
    int role = blockIdx.x % 5;
    int gid  = blockIdx.x / 5;
    int tid  = threadIdx.x;

    if (role < 2) {                            // ---- GEMM role ----
        int gemm_id = gid * 2 + role;          // 0..781
        for (int i = tid; i < F_IN * F_OUT; i += 128) Ws[i] = W[i];
        __syncthreads();

        int n = gemm_id * 128 + tid;
        if (n >= N_NODES) return;

        const float4* x4 = (const float4*)(x + (size_t)n * F_IN);
        float acc[F_OUT];
#pragma unroll
        for (int f = 0; f < F_OUT; f++) acc[f] = 0.f;

#pragma unroll
        for (int k4 = 0; k4 < F_IN / 4; k4++) {
            float4 xv = x4[k4];
            int k = k4 * 4;
#pragma unroll
            for (int f = 0; f < F_OUT; f++) {
                acc[f] += xv.x * Ws[(k + 0) * F_OUT + f];
                acc[f] += xv.y * Ws[(k + 1) * F_OUT + f];
                acc[f] += xv.z * Ws[(k + 2) * F_OUT + f];
                acc[f] += xv.w * Ws[(k + 3) * F_OUT + f];
            }
        }
        float4* gg = (float4*)(g_g + (size_t)n * F_OUT);
#pragma unroll
        for (int q = 0; q < 4; q++)
            gg[q] = make_float4(acc[q * 4 + 0], acc[q * 4 + 1],
                                acc[q * 4 + 2], acc[q * 4 + 3]);
    } else if (role < 4) {                     // ---- DEGREE role ----
        int deg_id = gid * 2 + (role - 2);     // 0..781
        int e = deg_id * 128 + tid;
#pragma unroll 4
        for (; e < N_EDGES; e += DEG_STRIDE) {
            int c = dst[e];
            atomicAdd(&g_deg[c], 1);           // REDG: fire-and-forget
        }
    } else {                                   // ---- ZERO role ----
        const float4 z4 = make_float4(0.f, 0.f, 0.f, 0.f);
        for (int i = gid * 128 + tid; i < N_NODES * F_OUT / 4;
             i += ZERO_IDS * 128)
            ((float4*)g_acc)[i] = z4;
        if (gid == 0 && tid < F_OUT) out[tid] = 0.0f;
    }
}

// ---------------- K2: dinv = rsqrt(deg+1); g *= dinv; reset deg ------------
__global__ void __launch_bounds__(256) k_dinv() {
    int n = blockIdx.x * 256 + threadIdx.x;
    if (n < N_NODES) {
        float dv = rsqrtf((float)(g_deg[n] + 1));   // +1 self loop
        g_dinv[n] = dv;
        g_deg[n] = 0;                          // restore invariant for replay
        float4* gg = (float4*)(g_g + (size_t)n * F_OUT);
#pragma unroll
        for (int q = 0; q < 4; q++) {
            float4 v = gg[q];
            gg[q] = make_float4(v.x * dv, v.y * dv, v.z * dv, v.w * dv);
        }
    }
}

// ---------------- K3: scatter g[src] into acc[dst] (R2-proven, at floor) ---
__global__ void __launch_bounds__(256) k_scatter(const int* __restrict__ src,
                                                 const int* __restrict__ dst) {
    long long t = (long long)blockIdx.x * blockDim.x + threadIdx.x;
    int e = (int)(t >> 2);
    int q = (int)(t & 3);
    if (e >= N_EDGES) return;
    int r = src[e];
    int c = dst[e];
    float4 v = ((const float4*)g_g)[r * 4 + q];
    float* p = g_acc + (size_t)c * F_OUT + q * 4;
    asm volatile("red.global.add.v4.f32 [%0], {%1,%2,%3,%4};"
                 :: "l"(p), "f"(v.x), "f"(v.y), "f"(v.z), "f"(v.w)
                 : "memory");
}

// ---------------- K4: finalize v2 — 4 threads/node, light reduction --------
// lane = (node_in_warp)*4 + q. Each thread: acc/g quad loads, 4 tanh, then
// 3 shfl rounds over node lanes; lanes 0-3 hold warp quad-sums -> smem[16]
// -> 16 global atomics per block (single-address REDG pipelines ~1/cyc).
#define FIN_TPB    256
#define FIN_BLOCKS ((4 * N_NODES + FIN_TPB - 1) / FIN_TPB)   // 1563

__global__ void __launch_bounds__(FIN_TPB) k_finalize(const float* __restrict__ b,
                                                      float* __restrict__ out) {
    __shared__ float sm[F_OUT];
    if (threadIdx.x < F_OUT) sm[threadIdx.x] = 0.f;
    __syncthreads();

    int t = blockIdx.x * FIN_TPB + threadIdx.x;
    int n = t >> 2;
    int q = t & 3;
    int lane = threadIdx.x & 31;

    float4 r = make_float4(0.f, 0.f, 0.f, 0.f);
    if (n < N_NODES) {
        float dv = g_dinv[n];                  // broadcast across 4 lanes
        float4 a = ((const float4*)g_acc)[n * 4 + q];
        float4 g = ((const float4*)g_g)[n * 4 + q];
        float4 bb = ((const float4*)b)[q];
        r.x = tanhf(dv * (a.x + g.x) + bb.x);
        r.y = tanhf(dv * (a.y + g.y) + bb.y);
        r.z = tanhf(dv * (a.z + g.z) + bb.z);
        r.w = tanhf(dv * (a.w + g.w) + bb.w);
    }

    // reduce over the 8 nodes in this warp (lane bits 2..4)
#pragma unroll
    for (int off = 16; off >= 4; off >>= 1) {
        r.x += __shfl_xor_sync(0xFFFFFFFFu, r.x, off);
        r.y += __shfl_xor_sync(0xFFFFFFFFu, r.y, off);
        r.z += __shfl_xor_sync(0xFFFFFFFFu, r.z, off);
        r.w += __shfl_xor_sync(0xFFFFFFFFu, r.w, off);
    }
    if (lane < 4) {                            // lane q holds quad-q warp sum
        atomicAdd(&sm[lane * 4 + 0], r.x);
        atomicAdd(&sm[lane * 4 + 1], r.y);
        atomicAdd(&sm[lane * 4 + 2], r.z);
        atomicAdd(&sm[lane * 4 + 3], r.w);
    }
    __syncthreads();
    if (threadIdx.x < F_OUT)
        atomicAdd(&out[threadIdx.x], sm[threadIdx.x] * (1.0f / (float)N_NODES));
}

// ---------------- launch ---------------------------------------------------
extern "C" void kernel_launch(void* const* d_in, const int* in_sizes, int n_in,
                              void* d_out, int out_size) {
    const float* x  = (const float*)d_in[0];
    const int*   ei = (const int*)d_in[1];   // [2, N_EDGES] int32 (JAX x64 off)
    const float* W  = (const float*)d_in[2];
    const float* b  = (const float*)d_in[3];
    float*       out = (float*)d_out;

    const int* src = ei;              // edge_index[0]
    const int* dst = ei + N_EDGES;    // edge_index[1]

    k_fused<<<FUSED_BLOCKS, 128>>>(x, W, dst, out);
    k_dinv <<<(N_NODES + 255) / 256, 256>>>();
    {
        long long threads = (long long)N_EDGES * 4;
        k_scatter<<<(int)((threads + 255) / 256), 256>>>(src, dst);
    }
    k_finalize<<<FIN_BLOCKS, FIN_TPB>>>(b, out);
}

// round 11
// speedup vs baseline: 1.0593x; 1.0593x over previous
#include <cuda_runtime.h>
#include <math.h>

#define N_NODES 100000
#define N_EDGES 6400000
#define F_IN    128
#define F_OUT   16

// ------------- device scratch (zero-init; invariants restored per call) ---
__device__ int   g_deg [N_NODES];            // in-deg from 0; k_dinv resets
__device__ float g_dinv[N_NODES];            // rsqrt(deg+1)
__device__ float g_g   [N_NODES * F_OUT];    // h=x@W (unscaled), then *dinv
__device__ float g_acc [N_NODES * F_OUT];    // scatter acc; zeroed in fused

// ---------------- K1: fused  gemm(h) || degree || zero  (R9-proven) --------
#define GEMM_IDS 782
#define DEG_IDS  782
#define ZERO_IDS 391
#define FUSED_BLOCKS (GEMM_IDS + DEG_IDS + ZERO_IDS)   // 1955
#define DEG_STRIDE (DEG_IDS * 128)                      // 100096 threads

__global__ void __launch_bounds__(128) k_fused(const float* __restrict__ x,
                                               const float* __restrict__ W,
                                               const int* __restrict__ dst,
                                               float* __restrict__ out) {
    __shared__ float4 Ws4[F_IN * F_OUT / 4];   // W rows as float4 (f quads)
    int role = blockIdx.x % 5;
    int gid  = blockIdx.x / 5;
    int tid  = threadIdx.x;

    if (role < 2) {                            // ---- GEMM role ----
        int gemm_id = gid * 2 + role;          // 0..781
        for (int i = tid; i < F_IN * F_OUT / 4; i += 128)
            Ws4[i] = ((const float4*)W)[i];
        __syncthreads();

        int n = gemm_id * 128 + tid;
        if (n >= N_NODES) return;

        const float4* x4 = (const float4*)(x + (size_t)n * F_IN);
        float4 a0 = make_float4(0.f, 0.f, 0.f, 0.f);
        float4 a1 = a0, a2 = a0, a3 = a0;

#pragma unroll
        for (int k4 = 0; k4 < F_IN / 4; k4++) {
            float4 xv = x4[k4];
            // row k: W[k][0..15] = Ws4[k*4 + 0..3]  (LDS.128, broadcast)
#pragma unroll
            for (int j = 0; j < 4; j++) {      // j = which of the 4 k's
                float xc = (j == 0) ? xv.x : (j == 1) ? xv.y
                         : (j == 2) ? xv.z : xv.w;
                int kb = (k4 * 4 + j) * 4;
                float4 w0 = Ws4[kb + 0];
                float4 w1 = Ws4[kb + 1];
                float4 w2 = Ws4[kb + 2];
                float4 w3 = Ws4[kb + 3];
                a0.x += xc * w0.x; a0.y += xc * w0.y;
                a0.z += xc * w0.z; a0.w += xc * w0.w;
                a1.x += xc * w1.x; a1.y += xc * w1.y;
                a1.z += xc * w1.z; a1.w += xc * w1.w;
                a2.x += xc * w2.x; a2.y += xc * w2.y;
                a2.z += xc * w2.z; a2.w += xc * w2.w;
                a3.x += xc * w3.x; a3.y += xc * w3.y;
                a3.z += xc * w3.z; a3.w += xc * w3.w;
            }
        }
        float4* gg = (float4*)(g_g + (size_t)n * F_OUT);
        gg[0] = a0; gg[1] = a1; gg[2] = a2; gg[3] = a3;
    } else if (role < 4) {                     // ---- DEGREE role ----
        int deg_id = gid * 2 + (role - 2);     // 0..781
        int e = deg_id * 128 + tid;
#pragma unroll 4
        for (; e < N_EDGES; e += DEG_STRIDE) {
            int c = dst[e];
            atomicAdd(&g_deg[c], 1);           // REDG: fire-and-forget
        }
    } else {                                   // ---- ZERO role ----
        const float4 z4 = make_float4(0.f, 0.f, 0.f, 0.f);
        for (int i = gid * 128 + tid; i < N_NODES * F_OUT / 4;
             i += ZERO_IDS * 128)
            ((float4*)g_acc)[i] = z4;
        if (gid == 0 && tid < F_OUT) out[tid] = 0.0f;
    }
}

// ---------------- K2: dinv v2 — 4 threads/node for latency hiding ----------
__global__ void __launch_bounds__(256) k_dinv() {
    int t = blockIdx.x * 256 + threadIdx.x;
    int n = t >> 2;
    int q = t & 3;
    if (n >= N_NODES) return;
    float dv = rsqrtf((float)(g_deg[n] + 1));  // +1 self loop (broadcast load)
    if (q == 0) {
        g_dinv[n] = dv;
        g_deg[n] = 0;                          // restore invariant for replay
    }
    float4* gg = (float4*)g_g + n * 4 + q;
    float4 v = *gg;
    *gg = make_float4(v.x * dv, v.y * dv, v.z * dv, v.w * dv);
}

// ---------------- K3: scatter g[src] into acc[dst] (R2-proven, at floor) ---
__global__ void __launch_bounds__(256) k_scatter(const int* __restrict__ src,
                                                 const int* __restrict__ dst) {
    long long t = (long long)blockIdx.x * blockDim.x + threadIdx.x;
    int e = (int)(t >> 2);
    int q = (int)(t & 3);
    if (e >= N_EDGES) return;
    int r = src[e];
    int c = dst[e];
    float4 v = ((const float4*)g_g)[r * 4 + q];
    float* p = g_acc + (size_t)c * F_OUT + q * 4;
    asm volatile("red.global.add.v4.f32 [%0], {%1,%2,%3,%4};"
                 :: "l"(p), "f"(v.x), "f"(v.y), "f"(v.z), "f"(v.w)
                 : "memory");
}

// ---------------- K4: finalize v2 (R10-proven, 8.0us) ----------------------
#define FIN_TPB    256
#define FIN_BLOCKS ((4 * N_NODES + FIN_TPB - 1) / FIN_TPB)   // 1563

__global__ void __launch_bounds__(FIN_TPB) k_finalize(const float* __restrict__ b,
                                                      float* __restrict__ out) {
    __shared__ float sm[F_OUT];
    if (threadIdx.x < F_OUT) sm[threadIdx.x] = 0.f;
    __syncthreads();

    int t = blockIdx.x * FIN_TPB + threadIdx.x;
    int n = t >> 2;
    int q = t & 3;
    int lane = threadIdx.x & 31;

    float4 r = make_float4(0.f, 0.f, 0.f, 0.f);
    if (n < N_NODES) {
        float dv = g_dinv[n];                  // broadcast across 4 lanes
        float4 a = ((const float4*)g_acc)[n * 4 + q];
        float4 g = ((const float4*)g_g)[n * 4 + q];
        float4 bb = ((const float4*)b)[q];
        r.x = tanhf(dv * (a.x + g.x) + bb.x);
        r.y = tanhf(dv * (a.y + g.y) + bb.y);
        r.z = tanhf(dv * (a.z + g.z) + bb.z);
        r.w = tanhf(dv * (a.w + g.w) + bb.w);
    }

#pragma unroll
    for (int off = 16; off >= 4; off >>= 1) {
        r.x += __shfl_xor_sync(0xFFFFFFFFu, r.x, off);
        r.y += __shfl_xor_sync(0xFFFFFFFFu, r.y, off);
        r.z += __shfl_xor_sync(0xFFFFFFFFu, r.z, off);
        r.w += __shfl_xor_sync(0xFFFFFFFFu, r.w, off);
    }
    if (lane < 4) {
        atomicAdd(&sm[lane * 4 + 0], r.x);
        atomicAdd(&sm[lane * 4 + 1], r.y);
        atomicAdd(&sm[lane * 4 + 2], r.z);
        atomicAdd(&sm[lane * 4 + 3], r.w);
    }
    __syncthreads();
    if (threadIdx.x < F_OUT)
        atomicAdd(&out[threadIdx.x], sm[threadIdx.x] * (1.0f / (float)N_NODES));
}

// ---------------- launch ---------------------------------------------------
extern "C" void kernel_launch(void* const* d_in, const int* in_sizes, int n_in,
                              void* d_out, int out_size) {
    const float* x  = (const float*)d_in[0];
    const int*   ei = (const int*)d_in[1];   // [2, N_EDGES] int32 (JAX x64 off)
    const float* W  = (const float*)d_in[2];
    const float* b  = (const float*)d_in[3];
    float*       out = (float*)d_out;

    const int* src = ei;              // edge_index[0]
    const int* dst = ei + N_EDGES;    // edge_index[1]

    k_fused<<<FUSED_BLOCKS, 128>>>(x, W, dst, out);
    k_dinv <<<(4 * N_NODES + 255) / 256, 256>>>();
    {
        long long threads = (long long)N_EDGES * 4;
        k_scatter<<<(int)((threads + 255) / 256), 256>>>(src, dst);
    }
    k_finalize<<<FIN_BLOCKS, FIN_TPB>>>(b, out);
}

// round 12
// speedup vs baseline: 1.0595x; 1.0002x over previous
#include <cuda_runtime.h>
#include <math.h>

#define N_NODES 100000
#define N_EDGES 6400000
#define F_IN    128
#define F_OUT   16

// ------------- device scratch (zero-init; invariants restored per call) ---
__device__ int   g_deg [N_NODES];            // in-deg from 0; k_dinv resets
__device__ float g_dinv[N_NODES];            // rsqrt(deg+1)
__device__ float g_g   [N_NODES * F_OUT];    // h=x@W (unscaled), then *dinv
__device__ float g_acc [N_NODES * F_OUT];    // scatter acc; zeroed in fused

// ---------------- K1: fused  gemm(h) || degree || zero  (R11-proven) -------
#define GEMM_IDS 782
#define DEG_IDS  782
#define ZERO_IDS 391
#define FUSED_BLOCKS (GEMM_IDS + DEG_IDS + ZERO_IDS)   // 1955
#define DEG_STRIDE (DEG_IDS * 128)                      // 100096 threads

__global__ void __launch_bounds__(128) k_fused(const float* __restrict__ x,
                                               const float* __restrict__ W,
                                               const int* __restrict__ dst,
                                               float* __restrict__ out) {
    __shared__ float4 Ws4[F_IN * F_OUT / 4];
    int role = blockIdx.x % 5;
    int gid  = blockIdx.x / 5;
    int tid  = threadIdx.x;

    if (role < 2) {                            // ---- GEMM role ----
        int gemm_id = gid * 2 + role;
        for (int i = tid; i < F_IN * F_OUT / 4; i += 128)
            Ws4[i] = ((const float4*)W)[i];
        __syncthreads();

        int n = gemm_id * 128 + tid;
        if (n >= N_NODES) return;

        const float4* x4 = (const float4*)(x + (size_t)n * F_IN);
        float4 a0 = make_float4(0.f, 0.f, 0.f, 0.f);
        float4 a1 = a0, a2 = a0, a3 = a0;

#pragma unroll
        for (int k4 = 0; k4 < F_IN / 4; k4++) {
            float4 xv = x4[k4];
#pragma unroll
            for (int j = 0; j < 4; j++) {
                float xc = (j == 0) ? xv.x : (j == 1) ? xv.y
                         : (j == 2) ? xv.z : xv.w;
                int kb = (k4 * 4 + j) * 4;
                float4 w0 = Ws4[kb + 0];
                float4 w1 = Ws4[kb + 1];
                float4 w2 = Ws4[kb + 2];
                float4 w3 = Ws4[kb + 3];
                a0.x += xc * w0.x; a0.y += xc * w0.y;
                a0.z += xc * w0.z; a0.w += xc * w0.w;
                a1.x += xc * w1.x; a1.y += xc * w1.y;
                a1.z += xc * w1.z; a1.w += xc * w1.w;
                a2.x += xc * w2.x; a2.y += xc * w2.y;
                a2.z += xc * w2.z; a2.w += xc * w2.w;
                a3.x += xc * w3.x; a3.y += xc * w3.y;
                a3.z += xc * w3.z; a3.w += xc * w3.w;
            }
        }
        float4* gg = (float4*)(g_g + (size_t)n * F_OUT);
        gg[0] = a0; gg[1] = a1; gg[2] = a2; gg[3] = a3;
    } else if (role < 4) {                     // ---- DEGREE role ----
        int deg_id = gid * 2 + (role - 2);
        int e = deg_id * 128 + tid;
#pragma unroll 4
        for (; e < N_EDGES; e += DEG_STRIDE) {
            int c = dst[e];
            atomicAdd(&g_deg[c], 1);
        }
    } else {                                   // ---- ZERO role ----
        const float4 z4 = make_float4(0.f, 0.f, 0.f, 0.f);
        for (int i = gid * 128 + tid; i < N_NODES * F_OUT / 4;
             i += ZERO_IDS * 128)
            ((float4*)g_acc)[i] = z4;
        if (gid == 0 && tid < F_OUT) out[tid] = 0.0f;
    }
}

// ---------------- K2: dinv v2 (R11-proven) + PDL sync ----------------------
__global__ void __launch_bounds__(256) k_dinv() {
    cudaGridDependencySynchronize();           // wait for k_fused results
    int t = blockIdx.x * 256 + threadIdx.x;
    int n = t >> 2;
    int q = t & 3;
    if (n >= N_NODES) return;
    float dv = rsqrtf((float)(g_deg[n] + 1));  // +1 self loop
    if (q == 0) {
        g_dinv[n] = dv;
        g_deg[n] = 0;                          // restore invariant for replay
    }
    float4* gg = (float4*)g_g + n * 4 + q;
    float4 v = *gg;
    *gg = make_float4(v.x * dv, v.y * dv, v.z * dv, v.w * dv);
}

// ---------------- K3: scatter (R2-proven core) + PDL index prefetch --------
__global__ void __launch_bounds__(256) k_scatter(const int* __restrict__ src,
                                                 const int* __restrict__ dst) {
    long long t = (long long)blockIdx.x * blockDim.x + threadIdx.x;
    int e = (int)(t >> 2);
    int q = (int)(t & 3);
    if (e >= N_EDGES) {
        cudaGridDependencySynchronize();
        return;
    }
    // prefetch indices (input data — independent of dinv/g) before sync
    int r = src[e];
    int c = dst[e];
    cudaGridDependencySynchronize();           // wait for k_dinv (g scaled)
    float4 v = ((const float4*)g_g)[r * 4 + q];
    float* p = g_acc + (size_t)c * F_OUT + q * 4;
    asm volatile("red.global.add.v4.f32 [%0], {%1,%2,%3,%4};"
                 :: "l"(p), "f"(v.x), "f"(v.y), "f"(v.z), "f"(v.w)
                 : "memory");
}

// ---------------- K4: finalize v2 (R10-proven) + PDL prefetch --------------
#define FIN_TPB    256
#define FIN_BLOCKS ((4 * N_NODES + FIN_TPB - 1) / FIN_TPB)   // 1563

__global__ void __launch_bounds__(FIN_TPB) k_finalize(const float* __restrict__ b,
                                                      float* __restrict__ out) {
    __shared__ float sm[F_OUT];
    if (threadIdx.x < F_OUT) sm[threadIdx.x] = 0.f;

    int t = blockIdx.x * FIN_TPB + threadIdx.x;
    int n = t >> 2;
    int q = t & 3;
    int lane = threadIdx.x & 31;

    // prefetch everything stable during scatter (scatter only writes g_acc)
    float dv = 0.f;
    float4 g = make_float4(0.f, 0.f, 0.f, 0.f);
    float4 bb = g;
    if (n < N_NODES) {
        dv = g_dinv[n];
        g  = ((const float4*)g_g)[n * 4 + q];
        bb = ((const float4*)b)[q];
    }
    cudaGridDependencySynchronize();           // wait for k_scatter (acc)
    __syncthreads();                           // sm[] zeroed + all synced

    float4 r = make_float4(0.f, 0.f, 0.f, 0.f);
    if (n < N_NODES) {
        float4 a = ((const float4*)g_acc)[n * 4 + q];
        r.x = tanhf(dv * (a.x + g.x) + bb.x);
        r.y = tanhf(dv * (a.y + g.y) + bb.y);
        r.z = tanhf(dv * (a.z + g.z) + bb.z);
        r.w = tanhf(dv * (a.w + g.w) + bb.w);
    }

#pragma unroll
    for (int off = 16; off >= 4; off >>= 1) {
        r.x += __shfl_xor_sync(0xFFFFFFFFu, r.x, off);
        r.y += __shfl_xor_sync(0xFFFFFFFFu, r.y, off);
        r.z += __shfl_xor_sync(0xFFFFFFFFu, r.z, off);
        r.w += __shfl_xor_sync(0xFFFFFFFFu, r.w, off);
    }
    if (lane < 4) {
        atomicAdd(&sm[lane * 4 + 0], r.x);
        atomicAdd(&sm[lane * 4 + 1], r.y);
        atomicAdd(&sm[lane * 4 + 2], r.z);
        atomicAdd(&sm[lane * 4 + 3], r.w);
    }
    __syncthreads();
    if (threadIdx.x < F_OUT)
        atomicAdd(&out[threadIdx.x], sm[threadIdx.x] * (1.0f / (float)N_NODES));
}

// ---------------- launch (PDL chain) ----------------------------------------
static void launch_pdl(void* func, dim3 grid, dim3 block,
                       void** args, cudaStream_t stream) {
    cudaLaunchAttribute attr[1];
    attr[0].id = cudaLaunchAttributeProgrammaticStreamSerialization;
    attr[0].val.programmaticStreamSerializationAllowed = 1;
    cudaLaunchConfig_t cfg;
    cfg.gridDim = grid;
    cfg.blockDim = block;
    cfg.dynamicSmemBytes = 0;
    cfg.stream = stream;
    cfg.attrs = attr;
    cfg.numAttrs = 1;
    cudaLaunchKernelExC(&cfg, func, args);
}

extern "C" void kernel_launch(void* const* d_in, const int* in_sizes, int n_in,
                              void* d_out, int out_size) {
    const float* x  = (const float*)d_in[0];
    const int*   ei = (const int*)d_in[1];   // [2, N_EDGES] int32 (JAX x64 off)
    const float* W  = (const float*)d_in[2];
    const float* b  = (const float*)d_in[3];
    float*       out = (float*)d_out;

    const int* src = ei;
    const int* dst = ei + N_EDGES;

    k_fused<<<FUSED_BLOCKS, 128>>>(x, W, dst, out);

    {   // dinv: PDL after fused
        void* args[] = {};
        launch_pdl((void*)k_dinv, dim3((4 * N_NODES + 255) / 256), dim3(256),
                   args, 0);
    }
    {   // scatter: PDL after dinv, prefetches indices pre-sync
        long long threads = (long long)N_EDGES * 4;
        void* args[] = {(void*)&src, (void*)&dst};
        launch_pdl((void*)k_scatter, dim3((int)((threads + 255) / 256)),
                   dim3(256), args, 0);
    }
    {   // finalize: PDL after scatter, prefetches dinv/g/b pre-sync
        void* args[] = {(void*)&b, (void*)&out};
        launch_pdl((void*)k_finalize, dim3(FIN_BLOCKS), dim3(FIN_TPB), args, 0);
    }
}